// round 2
// baseline (speedup 1.0000x reference)
#include <cuda_runtime.h>

#define D 256
#define MAXM 100096  // 100000 rounded up to multiple of 128

// ---------------- scratch (device globals; no allocations) ----------------
__device__ float g_h[(size_t)MAXM * D];   // current node features
__device__ float g_t[(size_t)MAXM * D];   // h + aggregated neighbors
__device__ float g_u[(size_t)MAXM * D];   // GEMM intermediate
__device__ float g_sum[D];
__device__ float g_sumsq[D];
__device__ float g_scale[D];
__device__ float g_shift[D];

// ---------------- small helpers ----------------
__global__ void zero_stats_kernel() {
    g_sum[threadIdx.x] = 0.f;
    g_sumsq[threadIdx.x] = 0.f;
}

// per-column sum & sumsq; block = 256 threads (one per column), grid-split rows
__global__ void stats_kernel(const float* __restrict__ X, int M) {
    int c = threadIdx.x;
    long long rows = (M + gridDim.x - 1) / gridDim.x;
    long long r0 = (long long)blockIdx.x * rows;
    long long r1 = r0 + rows;
    if (r1 > M) r1 = M;
    float s = 0.f, q = 0.f;
    for (long long r = r0; r < r1; r++) {
        float v = X[r * D + c];
        s += v;
        q += v * v;
    }
    if (r1 > r0) {
        atomicAdd(&g_sum[c], s);
        atomicAdd(&g_sumsq[c], q);
    }
}

// fold BN into y = x*scale + shift  (biased variance, eps=1e-5 like jnp.var)
__global__ void finalize_stats_kernel(const float* __restrict__ gamma,
                                      const float* __restrict__ beta, int M) {
    int c = threadIdx.x;
    float invM = 1.f / (float)M;
    float mu = g_sum[c] * invM;
    float var = g_sumsq[c] * invM - mu * mu;
    float sc = gamma[c] * rsqrtf(var + 1e-5f);
    g_scale[c] = sc;
    g_shift[c] = beta[c] - mu * sc;
}

// elementwise BN apply (+optional relu), optional second destination (copy)
__global__ void bn_apply_kernel(const float4* __restrict__ X, float4* __restrict__ O1,
                                float4* __restrict__ O2, long long n4, int relu) {
    long long i = (long long)blockIdx.x * blockDim.x + threadIdx.x;
    long long stride = (long long)gridDim.x * blockDim.x;
    const float4* sc4 = (const float4*)g_scale;
    const float4* sh4 = (const float4*)g_shift;
    for (; i < n4; i += stride) {
        int c4 = (int)(i & 63);  // row length = 64 float4
        float4 v = X[i];
        float4 s = sc4[c4];
        float4 h = sh4[c4];
        v.x = v.x * s.x + h.x;
        v.y = v.y * s.y + h.y;
        v.z = v.z * s.z + h.z;
        v.w = v.w * s.w + h.w;
        if (relu) {
            v.x = fmaxf(v.x, 0.f);
            v.y = fmaxf(v.y, 0.f);
            v.z = fmaxf(v.z, 0.f);
            v.w = fmaxf(v.w, 0.f);
        }
        O1[i] = v;
        if (O2) O2[i] = v;
    }
}

// ---------------- sparse aggregation: out[dst] += feat[src] ----------------
// 64 threads per edge, one float4 per thread, vector red (sm_90+ float4 atomicAdd)
__global__ void scatter_kernel(const float* __restrict__ feat, float* __restrict__ out,
                               const int* __restrict__ srcIdx,
                               const int* __restrict__ dstIdx, int E) {
    int e = blockIdx.x * 4 + (threadIdx.x >> 6);
    if (e >= E) return;
    int lane = threadIdx.x & 63;
    int s = __ldg(&srcIdx[e]);
    int d = __ldg(&dstIdx[e]);
    float4 v = *((const float4*)(feat + (size_t)s * D) + lane);
    atomicAdd((float4*)(out + (size_t)d * D) + lane, v);
}

// ---------------- SGEMM: C[M,256] = A[M,256] @ W[256,256] + bias ----------------
// BM=128, BN=128, BK=16, 256 threads, 8x8 register tile
__global__ __launch_bounds__(256) void gemm_kernel(
    const float* __restrict__ A, const float* __restrict__ W,
    const float* __restrict__ bias, float* __restrict__ C,
    float* __restrict__ C2, int M, int relu) {
    __shared__ float As[16][128];  // [k][m] (transposed on store)
    __shared__ float Bs[16][128];  // [k][n]

    int bm = blockIdx.x * 128;
    int bn = blockIdx.y * 128;
    int tid = threadIdx.x;

    int arow = tid >> 2;           // 0..63 (and +64)
    int acol4 = (tid & 3) << 2;    // k offset: 0,4,8,12
    int brow = tid >> 5;           // 0..7 (and +8)
    int bcol = (tid & 31) << 2;    // 0..124

    int ty = tid >> 4;             // 0..15, m-tile
    int tx = tid & 15;             // 0..15, n-tile

    float acc[8][8];
#pragma unroll
    for (int i = 0; i < 8; i++)
#pragma unroll
        for (int j = 0; j < 8; j++) acc[i][j] = 0.f;

    for (int k0 = 0; k0 < D; k0 += 16) {
#pragma unroll
        for (int i = 0; i < 2; i++) {
            int r = arow + i * 64;
            int gr = bm + r;
            float4 v = make_float4(0.f, 0.f, 0.f, 0.f);
            if (gr < M) v = *(const float4*)&A[(size_t)gr * D + k0 + acol4];
            As[acol4 + 0][r] = v.x;
            As[acol4 + 1][r] = v.y;
            As[acol4 + 2][r] = v.z;
            As[acol4 + 3][r] = v.w;
        }
#pragma unroll
        for (int i = 0; i < 2; i++) {
            int r = brow + i * 8;
            *(float4*)&Bs[r][bcol] = *(const float4*)&W[(size_t)(k0 + r) * D + bn + bcol];
        }
        __syncthreads();

#pragma unroll
        for (int k = 0; k < 16; k++) {
            float a[8], b[8];
#pragma unroll
            for (int i = 0; i < 8; i++) a[i] = As[k][ty * 8 + i];
#pragma unroll
            for (int j = 0; j < 8; j++) b[j] = Bs[k][tx * 8 + j];
#pragma unroll
            for (int i = 0; i < 8; i++)
#pragma unroll
                for (int j = 0; j < 8; j++) acc[i][j] += a[i] * b[j];
        }
        __syncthreads();
    }

#pragma unroll
    for (int i = 0; i < 8; i++) {
        int gr = bm + ty * 8 + i;
        if (gr >= M) break;
#pragma unroll
        for (int j = 0; j < 8; j += 4) {
            int gc = bn + tx * 8 + j;
            float4 o;
            o.x = acc[i][j + 0] + bias[gc + 0];
            o.y = acc[i][j + 1] + bias[gc + 1];
            o.z = acc[i][j + 2] + bias[gc + 2];
            o.w = acc[i][j + 3] + bias[gc + 3];
            if (relu) {
                o.x = fmaxf(o.x, 0.f);
                o.y = fmaxf(o.y, 0.f);
                o.z = fmaxf(o.z, 0.f);
                o.w = fmaxf(o.w, 0.f);
            }
            *(float4*)&C[(size_t)gr * D + gc] = o;
            if (C2) *(float4*)&C2[(size_t)gr * D + gc] = o;
        }
    }
}

// ---------------- driver ----------------
extern "C" void kernel_launch(void* const* d_in, const int* in_sizes, int n_in,
                              void* d_out, int out_size) {
    const float* x = (const float*)d_in[0];
    const int* ei = (const int*)d_in[1];   // JAX downcasts int64->int32 (x64 disabled)
    const float* g0 = (const float*)d_in[2];
    const float* b0 = (const float*)d_in[3];
    const float* W1a = (const float*)d_in[4];
    const float* b1a = (const float*)d_in[5];
    const float* g1 = (const float*)d_in[6];
    const float* bt1 = (const float*)d_in[7];
    const float* W1b = (const float*)d_in[8];
    const float* b1b = (const float*)d_in[9];
    const float* W2a = (const float*)d_in[10];
    const float* b2a = (const float*)d_in[11];
    const float* g2 = (const float*)d_in[12];
    const float* bt2 = (const float*)d_in[13];
    const float* W2b = (const float*)d_in[14];
    const float* b2b = (const float*)d_in[15];
    float* out = (float*)d_out;

    int M = in_sizes[0] / D;
    int E = in_sizes[1] / 2;
    const int* srcI = ei;
    const int* dstI = ei + E;

    float *h, *t, *u;
    cudaGetSymbolAddress((void**)&h, g_h);
    cudaGetSymbolAddress((void**)&t, g_t);
    cudaGetSymbolAddress((void**)&u, g_u);

    long long n4 = (long long)M * (D / 4);
    const int bnGrid = 2048;
    dim3 gemmGrid((M + 127) / 128, 2);
    int scGrid = (E + 3) / 4;

    // h = BN(x); t = h (scatter destination pre-init)
    zero_stats_kernel<<<1, 256>>>();
    stats_kernel<<<512, 256>>>(x, M);
    finalize_stats_kernel<<<1, 256>>>(g0, b0, M);
    bn_apply_kernel<<<bnGrid, 256>>>((const float4*)x, (float4*)h, (float4*)t, n4, 0);

    // ---- conv1 ----
    scatter_kernel<<<scGrid, 256>>>(h, t, srcI, dstI, E);              // t = h + agg(h)
    gemm_kernel<<<gemmGrid, 256>>>(t, W1a, b1a, u, nullptr, M, 0);     // u = t@W1a + b1a
    zero_stats_kernel<<<1, 256>>>();
    stats_kernel<<<512, 256>>>(u, M);
    finalize_stats_kernel<<<1, 256>>>(g1, bt1, M);
    bn_apply_kernel<<<bnGrid, 256>>>((const float4*)u, (float4*)u, nullptr, n4, 1);  // relu(BN(u))
    gemm_kernel<<<gemmGrid, 256>>>(u, W1b, b1b, h, t, M, 1);           // h = relu(u@W1b+b); t = h

    // ---- conv2 ----
    scatter_kernel<<<scGrid, 256>>>(h, t, srcI, dstI, E);              // t = h + agg(h)
    gemm_kernel<<<gemmGrid, 256>>>(t, W2a, b2a, u, nullptr, M, 0);
    zero_stats_kernel<<<1, 256>>>();
    stats_kernel<<<512, 256>>>(u, M);
    finalize_stats_kernel<<<1, 256>>>(g2, bt2, M);
    bn_apply_kernel<<<bnGrid, 256>>>((const float4*)u, (float4*)u, nullptr, n4, 1);
    gemm_kernel<<<gemmGrid, 256>>>(u, W2b, b2b, out, nullptr, M, 1);   // out = relu(u@W2b+b)
}

// round 4
// speedup vs baseline: 1.1886x; 1.1886x over previous
#include <cuda_runtime.h>
#include <cuda_bf16.h>
#include <cstdint>

#define D 256
#define MAXM 100096  // 100000 rounded up to multiple of 128

// ---------------- scratch (device globals; no allocations) ----------------
__device__ float g_h[(size_t)MAXM * D];   // current node features
__device__ float g_t[(size_t)MAXM * D];   // h + aggregated neighbors
__device__ float g_u[(size_t)MAXM * D];   // GEMM intermediate
__device__ float g_sum[D];
__device__ float g_sumsq[D];
__device__ float g_scale[D];
__device__ float g_shift[D];

// ---------------- small helpers ----------------
__global__ void zero_stats_kernel() {
    g_sum[threadIdx.x] = 0.f;
    g_sumsq[threadIdx.x] = 0.f;
}

__global__ void stats_kernel(const float* __restrict__ X, int M) {
    int c = threadIdx.x;
    long long rows = (M + gridDim.x - 1) / gridDim.x;
    long long r0 = (long long)blockIdx.x * rows;
    long long r1 = r0 + rows;
    if (r1 > M) r1 = M;
    float s = 0.f, q = 0.f;
    for (long long r = r0; r < r1; r++) {
        float v = X[r * D + c];
        s += v;
        q += v * v;
    }
    if (r1 > r0) {
        atomicAdd(&g_sum[c], s);
        atomicAdd(&g_sumsq[c], q);
    }
}

__global__ void finalize_stats_kernel(const float* __restrict__ gamma,
                                      const float* __restrict__ beta, int M) {
    int c = threadIdx.x;
    float invM = 1.f / (float)M;
    float mu = g_sum[c] * invM;
    float var = g_sumsq[c] * invM - mu * mu;
    float sc = gamma[c] * rsqrtf(var + 1e-5f);
    g_scale[c] = sc;
    g_shift[c] = beta[c] - mu * sc;
}

__global__ void bn_apply_kernel(const float4* __restrict__ X, float4* __restrict__ O1,
                                float4* __restrict__ O2, long long n4, int relu) {
    long long i = (long long)blockIdx.x * blockDim.x + threadIdx.x;
    long long stride = (long long)gridDim.x * blockDim.x;
    const float4* sc4 = (const float4*)g_scale;
    const float4* sh4 = (const float4*)g_shift;
    for (; i < n4; i += stride) {
        int c4 = (int)(i & 63);
        float4 v = X[i];
        float4 s = sc4[c4];
        float4 h = sh4[c4];
        v.x = v.x * s.x + h.x;
        v.y = v.y * s.y + h.y;
        v.z = v.z * s.z + h.z;
        v.w = v.w * s.w + h.w;
        if (relu) {
            v.x = fmaxf(v.x, 0.f);
            v.y = fmaxf(v.y, 0.f);
            v.z = fmaxf(v.z, 0.f);
            v.w = fmaxf(v.w, 0.f);
        }
        O1[i] = v;
        if (O2) O2[i] = v;
    }
}

// ---------------- sparse aggregation: out[dst] += feat[src] ----------------
__global__ void scatter_kernel(const float* __restrict__ feat, float* __restrict__ out,
                               const int* __restrict__ srcIdx,
                               const int* __restrict__ dstIdx, int E) {
    int e = blockIdx.x * 4 + (threadIdx.x >> 6);
    if (e >= E) return;
    int lane = threadIdx.x & 63;
    int s = __ldg(&srcIdx[e]);
    int d = __ldg(&dstIdx[e]);
    float4 v = *((const float4*)(feat + (size_t)s * D) + lane);
    atomicAdd((float4*)(out + (size_t)d * D) + lane, v);
}

// ---------------- tensor-core GEMM (bf16x3 split, fp32 accum) ----------------
// C[M,256] = A[M,256] @ W[256,256] + bias ; block tile 128x128, BK=32
// 8 warps arranged 2(m) x 4(n); warp tile 64x32; mma.m16n8k16
#define BK 32
#define AS 40    // As row stride (elements)
#define BS 136   // Bs row stride (elements)

__global__ __launch_bounds__(256, 1) void gemm_tc_kernel(
    const float* __restrict__ A, const float* __restrict__ W,
    const float* __restrict__ bias, float* __restrict__ C,
    float* __restrict__ C2, int M, int relu) {
    __shared__ __nv_bfloat16 As_h[128 * AS];
    __shared__ __nv_bfloat16 As_l[128 * AS];
    __shared__ __nv_bfloat16 Bs_h[BK * BS];
    __shared__ __nv_bfloat16 Bs_l[BK * BS];

    int bm = blockIdx.x * 128;
    int bn = blockIdx.y * 128;
    int tid = threadIdx.x;
    int lane = tid & 31;
    int wid = tid >> 5;
    int warp_m = wid >> 2;   // 0..1
    int warp_n = wid & 3;    // 0..3

    float acc[4][4][4];
#pragma unroll
    for (int i = 0; i < 4; i++)
#pragma unroll
        for (int j = 0; j < 4; j++)
#pragma unroll
            for (int r = 0; r < 4; r++) acc[i][j][r] = 0.f;

    // A loader coords: 2 threads per row, 16 k-elems each (4 float4)
    int a_row = tid >> 1;
    int a_kb = (tid & 1) * 16;
    bool a_valid = (bm + a_row) < M;
    // B loader coords: 8 threads per row, 16 n-elems each
    int b_row = tid >> 3;
    int b_cb = (tid & 7) * 16;

    uint32_t as_h_base = (uint32_t)__cvta_generic_to_shared(As_h);
    uint32_t as_l_base = (uint32_t)__cvta_generic_to_shared(As_l);
    uint32_t bs_h_base = (uint32_t)__cvta_generic_to_shared(Bs_h);
    uint32_t bs_l_base = (uint32_t)__cvta_generic_to_shared(Bs_l);

    for (int k0 = 0; k0 < D; k0 += BK) {
        // ---- load A tile (128 x BK) with hi/lo split ----
        {
            const float* Ar = A + (size_t)(bm + a_row) * D + k0 + a_kb;
#pragma unroll
            for (int i = 0; i < 4; i++) {
                float4 v = a_valid ? *(const float4*)(Ar + i * 4)
                                   : make_float4(0.f, 0.f, 0.f, 0.f);
                __nv_bfloat162 h01 = __floats2bfloat162_rn(v.x, v.y);
                __nv_bfloat162 h23 = __floats2bfloat162_rn(v.z, v.w);
                float2 f01 = __bfloat1622float2(h01);
                float2 f23 = __bfloat1622float2(h23);
                __nv_bfloat162 l01 = __floats2bfloat162_rn(v.x - f01.x, v.y - f01.y);
                __nv_bfloat162 l23 = __floats2bfloat162_rn(v.z - f23.x, v.w - f23.y);
                int off = a_row * AS + a_kb + i * 4;
                *(__nv_bfloat162*)&As_h[off] = h01;
                *(__nv_bfloat162*)&As_h[off + 2] = h23;
                *(__nv_bfloat162*)&As_l[off] = l01;
                *(__nv_bfloat162*)&As_l[off + 2] = l23;
            }
        }
        // ---- load B tile (BK x 128) with hi/lo split ----
        {
            const float* Wr = W + (size_t)(k0 + b_row) * D + bn + b_cb;
#pragma unroll
            for (int i = 0; i < 4; i++) {
                float4 v = *(const float4*)(Wr + i * 4);
                __nv_bfloat162 h01 = __floats2bfloat162_rn(v.x, v.y);
                __nv_bfloat162 h23 = __floats2bfloat162_rn(v.z, v.w);
                float2 f01 = __bfloat1622float2(h01);
                float2 f23 = __bfloat1622float2(h23);
                __nv_bfloat162 l01 = __floats2bfloat162_rn(v.x - f01.x, v.y - f01.y);
                __nv_bfloat162 l23 = __floats2bfloat162_rn(v.z - f23.x, v.w - f23.y);
                int off = b_row * BS + b_cb + i * 4;
                *(__nv_bfloat162*)&Bs_h[off] = h01;
                *(__nv_bfloat162*)&Bs_h[off + 2] = h23;
                *(__nv_bfloat162*)&Bs_l[off] = l01;
                *(__nv_bfloat162*)&Bs_l[off + 2] = l23;
            }
        }
        __syncthreads();

#pragma unroll
        for (int k16 = 0; k16 < BK; k16 += 16) {
            uint32_t ah[4][4];
            uint32_t al[4][4];
            uint32_t bh[4][2];
            uint32_t bl[4][2];
            // A fragments: 4 m16 tiles
#pragma unroll
            for (int mi = 0; mi < 4; mi++) {
                int row = warp_m * 64 + mi * 16 + (lane & 15);
                int col = k16 + ((lane >> 4) << 3);
                uint32_t ad = as_h_base + (uint32_t)(row * AS + col) * 2;
                asm volatile("ldmatrix.sync.aligned.m8n8.x4.shared.b16 {%0,%1,%2,%3}, [%4];"
                             : "=r"(ah[mi][0]), "=r"(ah[mi][1]), "=r"(ah[mi][2]), "=r"(ah[mi][3])
                             : "r"(ad));
                uint32_t ad2 = as_l_base + (uint32_t)(row * AS + col) * 2;
                asm volatile("ldmatrix.sync.aligned.m8n8.x4.shared.b16 {%0,%1,%2,%3}, [%4];"
                             : "=r"(al[mi][0]), "=r"(al[mi][1]), "=r"(al[mi][2]), "=r"(al[mi][3])
                             : "r"(ad2));
            }
            // B fragments: 4 n8 tiles
#pragma unroll
            for (int ni = 0; ni < 4; ni++) {
                int row = k16 + (lane & 15);
                int col = warp_n * 32 + ni * 8;
                uint32_t bd = bs_h_base + (uint32_t)(row * BS + col) * 2;
                asm volatile("ldmatrix.sync.aligned.m8n8.x2.trans.shared.b16 {%0,%1}, [%2];"
                             : "=r"(bh[ni][0]), "=r"(bh[ni][1]) : "r"(bd));
                uint32_t bd2 = bs_l_base + (uint32_t)(row * BS + col) * 2;
                asm volatile("ldmatrix.sync.aligned.m8n8.x2.trans.shared.b16 {%0,%1}, [%2];"
                             : "=r"(bl[ni][0]), "=r"(bl[ni][1]) : "r"(bd2));
            }
#pragma unroll
            for (int mi = 0; mi < 4; mi++) {
#pragma unroll
                for (int ni = 0; ni < 4; ni++) {
                    float* d = acc[mi][ni];
                    asm volatile(
                        "mma.sync.aligned.m16n8k16.row.col.f32.bf16.bf16.f32 "
                        "{%0,%1,%2,%3}, {%4,%5,%6,%7}, {%8,%9}, {%0,%1,%2,%3};"
                        : "+f"(d[0]), "+f"(d[1]), "+f"(d[2]), "+f"(d[3])
                        : "r"(ah[mi][0]), "r"(ah[mi][1]), "r"(ah[mi][2]), "r"(ah[mi][3]),
                          "r"(bh[ni][0]), "r"(bh[ni][1]));
                    asm volatile(
                        "mma.sync.aligned.m16n8k16.row.col.f32.bf16.bf16.f32 "
                        "{%0,%1,%2,%3}, {%4,%5,%6,%7}, {%8,%9}, {%0,%1,%2,%3};"
                        : "+f"(d[0]), "+f"(d[1]), "+f"(d[2]), "+f"(d[3])
                        : "r"(ah[mi][0]), "r"(ah[mi][1]), "r"(ah[mi][2]), "r"(ah[mi][3]),
                          "r"(bl[ni][0]), "r"(bl[ni][1]));
                    asm volatile(
                        "mma.sync.aligned.m16n8k16.row.col.f32.bf16.bf16.f32 "
                        "{%0,%1,%2,%3}, {%4,%5,%6,%7}, {%8,%9}, {%0,%1,%2,%3};"
                        : "+f"(d[0]), "+f"(d[1]), "+f"(d[2]), "+f"(d[3])
                        : "r"(al[mi][0]), "r"(al[mi][1]), "r"(al[mi][2]), "r"(al[mi][3]),
                          "r"(bh[ni][0]), "r"(bh[ni][1]));
                }
            }
        }
        __syncthreads();
    }

    // ---- epilogue: bias + optional relu + (dual) store ----
#pragma unroll
    for (int mi = 0; mi < 4; mi++) {
#pragma unroll
        for (int ni = 0; ni < 4; ni++) {
            int r0 = bm + warp_m * 64 + mi * 16 + (lane >> 2);
            int c0 = bn + warp_n * 32 + ni * 8 + (lane & 3) * 2;
            float b0 = bias[c0], b1 = bias[c0 + 1];
            float* d = acc[mi][ni];
            float2 v0 = make_float2(d[0] + b0, d[1] + b1);
            float2 v1 = make_float2(d[2] + b0, d[3] + b1);
            if (relu) {
                v0.x = fmaxf(v0.x, 0.f); v0.y = fmaxf(v0.y, 0.f);
                v1.x = fmaxf(v1.x, 0.f); v1.y = fmaxf(v1.y, 0.f);
            }
            if (r0 < M) {
                *(float2*)&C[(size_t)r0 * D + c0] = v0;
                if (C2) *(float2*)&C2[(size_t)r0 * D + c0] = v0;
            }
            if (r0 + 8 < M) {
                *(float2*)&C[(size_t)(r0 + 8) * D + c0] = v1;
                if (C2) *(float2*)&C2[(size_t)(r0 + 8) * D + c0] = v1;
            }
        }
    }
}

// ---------------- driver ----------------
extern "C" void kernel_launch(void* const* d_in, const int* in_sizes, int n_in,
                              void* d_out, int out_size) {
    const float* x = (const float*)d_in[0];
    const int* ei = (const int*)d_in[1];   // int32 (JAX x64 disabled)
    const float* g0 = (const float*)d_in[2];
    const float* b0 = (const float*)d_in[3];
    const float* W1a = (const float*)d_in[4];
    const float* b1a = (const float*)d_in[5];
    const float* g1 = (const float*)d_in[6];
    const float* bt1 = (const float*)d_in[7];
    const float* W1b = (const float*)d_in[8];
    const float* b1b = (const float*)d_in[9];
    const float* W2a = (const float*)d_in[10];
    const float* b2a = (const float*)d_in[11];
    const float* g2 = (const float*)d_in[12];
    const float* bt2 = (const float*)d_in[13];
    const float* W2b = (const float*)d_in[14];
    const float* b2b = (const float*)d_in[15];
    float* out = (float*)d_out;

    int M = in_sizes[0] / D;
    int E = in_sizes[1] / 2;
    const int* srcI = ei;
    const int* dstI = ei + E;

    float *h, *t, *u;
    cudaGetSymbolAddress((void**)&h, g_h);
    cudaGetSymbolAddress((void**)&t, g_t);
    cudaGetSymbolAddress((void**)&u, g_u);

    long long n4 = (long long)M * (D / 4);
    const int bnGrid = 2048;
    dim3 gemmGrid((M + 127) / 128, 2);
    int scGrid = (E + 3) / 4;

    // h = BN(x); t = h (scatter destination pre-init)
    zero_stats_kernel<<<1, 256>>>();
    stats_kernel<<<512, 256>>>(x, M);
    finalize_stats_kernel<<<1, 256>>>(g0, b0, M);
    bn_apply_kernel<<<bnGrid, 256>>>((const float4*)x, (float4*)h, (float4*)t, n4, 0);

    // ---- conv1 ----
    scatter_kernel<<<scGrid, 256>>>(h, t, srcI, dstI, E);                 // t = h + agg(h)
    gemm_tc_kernel<<<gemmGrid, 256>>>(t, W1a, b1a, u, nullptr, M, 0);     // u = t@W1a + b1a
    zero_stats_kernel<<<1, 256>>>();
    stats_kernel<<<512, 256>>>(u, M);
    finalize_stats_kernel<<<1, 256>>>(g1, bt1, M);
    bn_apply_kernel<<<bnGrid, 256>>>((const float4*)u, (float4*)u, nullptr, n4, 1);
    gemm_tc_kernel<<<gemmGrid, 256>>>(u, W1b, b1b, h, t, M, 1);           // h = relu(...); t = h

    // ---- conv2 ----
    scatter_kernel<<<scGrid, 256>>>(h, t, srcI, dstI, E);                 // t = h + agg(h)
    gemm_tc_kernel<<<gemmGrid, 256>>>(t, W2a, b2a, u, nullptr, M, 0);
    zero_stats_kernel<<<1, 256>>>();
    stats_kernel<<<512, 256>>>(u, M);
    finalize_stats_kernel<<<1, 256>>>(g2, bt2, M);
    bn_apply_kernel<<<bnGrid, 256>>>((const float4*)u, (float4*)u, nullptr, n4, 1);
    gemm_tc_kernel<<<gemmGrid, 256>>>(u, W2b, b2b, out, nullptr, M, 1);   // out = relu(...)
}

// round 6
// speedup vs baseline: 1.7905x; 1.5064x over previous
#include <cuda_runtime.h>
#include <cuda_bf16.h>
#include <cstdint>

#define D 256
#define MAXM 100096   // >= N, multiple of 128
#define MAXE 1700000
#define SCANB 1024
#define MAXSB 128     // >= MAXM/SCANB

// ---------------- scratch (device globals; no allocations) ----------------
__device__ float g_h[(size_t)MAXM * D];   // current node features
__device__ float g_t[(size_t)MAXM * D];   // h + aggregated neighbors
__device__ float g_u[(size_t)MAXM * D];   // GEMM intermediate
__device__ float g_sum[D];
__device__ float g_sumsq[D];
__device__ float g_scale[D];
__device__ float g_shift[D];
// CSR scratch
__device__ int g_deg[MAXM];
__device__ int g_cursor[MAXM];
__device__ int g_rowptr[MAXM + 1];
__device__ int g_col[MAXE];
__device__ int g_bsum[MAXSB];

// ---------------- BN helpers ----------------
__global__ void zero_stats_kernel() {
    g_sum[threadIdx.x] = 0.f;
    g_sumsq[threadIdx.x] = 0.f;
}

__global__ void stats_kernel(const float* __restrict__ X, int M) {
    int c = threadIdx.x;
    long long rows = (M + gridDim.x - 1) / gridDim.x;
    long long r0 = (long long)blockIdx.x * rows;
    long long r1 = r0 + rows;
    if (r1 > M) r1 = M;
    float s = 0.f, q = 0.f;
    for (long long r = r0; r < r1; r++) {
        float v = X[r * D + c];
        s += v;
        q += v * v;
    }
    if (r1 > r0) {
        atomicAdd(&g_sum[c], s);
        atomicAdd(&g_sumsq[c], q);
    }
}

__global__ void finalize_stats_kernel(const float* __restrict__ gamma,
                                      const float* __restrict__ beta, int M) {
    int c = threadIdx.x;
    float invM = 1.f / (float)M;
    float mu = g_sum[c] * invM;
    float var = g_sumsq[c] * invM - mu * mu;
    float sc = gamma[c] * rsqrtf(var + 1e-5f);
    g_scale[c] = sc;
    g_shift[c] = beta[c] - mu * sc;
}

__global__ void bn_apply_kernel(const float4* __restrict__ X, float4* __restrict__ O1,
                                long long n4, int relu) {
    long long i = (long long)blockIdx.x * blockDim.x + threadIdx.x;
    long long stride = (long long)gridDim.x * blockDim.x;
    const float4* sc4 = (const float4*)g_scale;
    const float4* sh4 = (const float4*)g_shift;
    for (; i < n4; i += stride) {
        int c4 = (int)(i & 63);
        float4 v = X[i];
        float4 s = sc4[c4];
        float4 h = sh4[c4];
        v.x = v.x * s.x + h.x;
        v.y = v.y * s.y + h.y;
        v.z = v.z * s.z + h.z;
        v.w = v.w * s.w + h.w;
        if (relu) {
            v.x = fmaxf(v.x, 0.f);
            v.y = fmaxf(v.y, 0.f);
            v.z = fmaxf(v.z, 0.f);
            v.w = fmaxf(v.w, 0.f);
        }
        O1[i] = v;
    }
}

// ---------------- CSR build (once per launch; reused by both convs) ----------------
__global__ void zero_deg_kernel(int M) {
    int i = blockIdx.x * blockDim.x + threadIdx.x;
    if (i < M) {
        g_deg[i] = 0;
        g_cursor[i] = 0;
    }
}

__global__ void hist_kernel(const int* __restrict__ dstIdx, int E) {
    int e = blockIdx.x * blockDim.x + threadIdx.x;
    if (e < E) atomicAdd(&g_deg[dstIdx[e]], 1);
}

__global__ void scan_block_kernel(int M) {
    __shared__ int sh[SCANB];
    int i = blockIdx.x * SCANB + threadIdx.x;
    int v = (i < M) ? g_deg[i] : 0;
    sh[threadIdx.x] = v;
    __syncthreads();
    for (int off = 1; off < SCANB; off <<= 1) {
        int t = (threadIdx.x >= off) ? sh[threadIdx.x - off] : 0;
        __syncthreads();
        sh[threadIdx.x] += t;
        __syncthreads();
    }
    if (i < M) g_rowptr[i] = sh[threadIdx.x] - v;  // exclusive within block
    if (threadIdx.x == SCANB - 1) g_bsum[blockIdx.x] = sh[SCANB - 1];
}

__global__ void scan_bsum_kernel(int nb) {
    if (threadIdx.x == 0) {
        int run = 0;
        for (int i = 0; i < nb; i++) {
            int v = g_bsum[i];
            g_bsum[i] = run;
            run += v;
        }
    }
}

__global__ void scan_add_kernel(int M, int E) {
    int i = blockIdx.x * SCANB + threadIdx.x;
    if (i < M) g_rowptr[i] += g_bsum[blockIdx.x];
    if (i == 0) g_rowptr[M] = E;
}

__global__ void fill_kernel(const int* __restrict__ srcIdx,
                            const int* __restrict__ dstIdx, int E) {
    int e = blockIdx.x * blockDim.x + threadIdx.x;
    if (e >= E) return;
    int d = dstIdx[e];
    int pos = g_rowptr[d] + atomicAdd(&g_cursor[d], 1);
    g_col[pos] = srcIdx[e];
}

// ---------------- CSR aggregation: out[i] = feat[i] + sum_{j in N(i)} feat[j] ----
// 64 threads per node (one float4 column each), 4 nodes per 256-thread block
__global__ void agg_csr_kernel(const float* __restrict__ feat,
                               float* __restrict__ out, int M) {
    int node = blockIdx.x * 4 + (threadIdx.x >> 6);
    if (node >= M) return;
    int lane = threadIdx.x & 63;
    int e0 = __ldg(&g_rowptr[node]);
    int e1 = __ldg(&g_rowptr[node + 1]);
    const float4* base = (const float4*)feat;
    float4 acc = base[(size_t)node * 64 + lane];  // self term
    int e = e0;
    for (; e + 4 <= e1; e += 4) {
        int s0 = __ldg(&g_col[e + 0]);
        int s1 = __ldg(&g_col[e + 1]);
        int s2 = __ldg(&g_col[e + 2]);
        int s3 = __ldg(&g_col[e + 3]);
        float4 v0 = base[(size_t)s0 * 64 + lane];
        float4 v1 = base[(size_t)s1 * 64 + lane];
        float4 v2 = base[(size_t)s2 * 64 + lane];
        float4 v3 = base[(size_t)s3 * 64 + lane];
        acc.x += (v0.x + v1.x) + (v2.x + v3.x);
        acc.y += (v0.y + v1.y) + (v2.y + v3.y);
        acc.z += (v0.z + v1.z) + (v2.z + v3.z);
        acc.w += (v0.w + v1.w) + (v2.w + v3.w);
    }
    for (; e < e1; e++) {
        int s = __ldg(&g_col[e]);
        float4 v = base[(size_t)s * 64 + lane];
        acc.x += v.x;
        acc.y += v.y;
        acc.z += v.z;
        acc.w += v.w;
    }
    ((float4*)out)[(size_t)node * 64 + lane] = acc;
}

// ---------------- tensor-core GEMM (bf16x3 split, fp32 accum) ----------------
#define BK 32
#define AS 40    // As row stride (elements)
#define BS 136   // Bs row stride (elements)

__global__ __launch_bounds__(256, 1) void gemm_tc_kernel(
    const float* __restrict__ A, const float* __restrict__ W,
    const float* __restrict__ bias, float* __restrict__ C,
    int M, int relu) {
    __shared__ __nv_bfloat16 As_h[128 * AS];
    __shared__ __nv_bfloat16 As_l[128 * AS];
    __shared__ __nv_bfloat16 Bs_h[BK * BS];
    __shared__ __nv_bfloat16 Bs_l[BK * BS];

    int bm = blockIdx.x * 128;
    int bn = blockIdx.y * 128;
    int tid = threadIdx.x;
    int lane = tid & 31;
    int wid = tid >> 5;
    int warp_m = wid >> 2;   // 0..1
    int warp_n = wid & 3;    // 0..3

    float acc[4][4][4];
#pragma unroll
    for (int i = 0; i < 4; i++)
#pragma unroll
        for (int j = 0; j < 4; j++)
#pragma unroll
            for (int r = 0; r < 4; r++) acc[i][j][r] = 0.f;

    int a_row = tid >> 1;
    int a_kb = (tid & 1) * 16;
    bool a_valid = (bm + a_row) < M;
    int b_row = tid >> 3;
    int b_cb = (tid & 7) * 16;

    uint32_t as_h_base = (uint32_t)__cvta_generic_to_shared(As_h);
    uint32_t as_l_base = (uint32_t)__cvta_generic_to_shared(As_l);
    uint32_t bs_h_base = (uint32_t)__cvta_generic_to_shared(Bs_h);
    uint32_t bs_l_base = (uint32_t)__cvta_generic_to_shared(Bs_l);

    for (int k0 = 0; k0 < D; k0 += BK) {
        {
            const float* Ar = A + (size_t)(bm + a_row) * D + k0 + a_kb;
#pragma unroll
            for (int i = 0; i < 4; i++) {
                float4 v = a_valid ? *(const float4*)(Ar + i * 4)
                                   : make_float4(0.f, 0.f, 0.f, 0.f);
                __nv_bfloat162 h01 = __floats2bfloat162_rn(v.x, v.y);
                __nv_bfloat162 h23 = __floats2bfloat162_rn(v.z, v.w);
                float2 f01 = __bfloat1622float2(h01);
                float2 f23 = __bfloat1622float2(h23);
                __nv_bfloat162 l01 = __floats2bfloat162_rn(v.x - f01.x, v.y - f01.y);
                __nv_bfloat162 l23 = __floats2bfloat162_rn(v.z - f23.x, v.w - f23.y);
                int off = a_row * AS + a_kb + i * 4;
                *(__nv_bfloat162*)&As_h[off] = h01;
                *(__nv_bfloat162*)&As_h[off + 2] = h23;
                *(__nv_bfloat162*)&As_l[off] = l01;
                *(__nv_bfloat162*)&As_l[off + 2] = l23;
            }
        }
        {
            const float* Wr = W + (size_t)(k0 + b_row) * D + bn + b_cb;
#pragma unroll
            for (int i = 0; i < 4; i++) {
                float4 v = *(const float4*)(Wr + i * 4);
                __nv_bfloat162 h01 = __floats2bfloat162_rn(v.x, v.y);
                __nv_bfloat162 h23 = __floats2bfloat162_rn(v.z, v.w);
                float2 f01 = __bfloat1622float2(h01);
                float2 f23 = __bfloat1622float2(h23);
                __nv_bfloat162 l01 = __floats2bfloat162_rn(v.x - f01.x, v.y - f01.y);
                __nv_bfloat162 l23 = __floats2bfloat162_rn(v.z - f23.x, v.w - f23.y);
                int off = b_row * BS + b_cb + i * 4;
                *(__nv_bfloat162*)&Bs_h[off] = h01;
                *(__nv_bfloat162*)&Bs_h[off + 2] = h23;
                *(__nv_bfloat162*)&Bs_l[off] = l01;
                *(__nv_bfloat162*)&Bs_l[off + 2] = l23;
            }
        }
        __syncthreads();

#pragma unroll
        for (int k16 = 0; k16 < BK; k16 += 16) {
            uint32_t ah[4][4];
            uint32_t al[4][4];
            uint32_t bh[4][2];
            uint32_t bl[4][2];
#pragma unroll
            for (int mi = 0; mi < 4; mi++) {
                int row = warp_m * 64 + mi * 16 + (lane & 15);
                int col = k16 + ((lane >> 4) << 3);
                uint32_t ad = as_h_base + (uint32_t)(row * AS + col) * 2;
                asm volatile("ldmatrix.sync.aligned.m8n8.x4.shared.b16 {%0,%1,%2,%3}, [%4];"
                             : "=r"(ah[mi][0]), "=r"(ah[mi][1]), "=r"(ah[mi][2]), "=r"(ah[mi][3])
                             : "r"(ad));
                uint32_t ad2 = as_l_base + (uint32_t)(row * AS + col) * 2;
                asm volatile("ldmatrix.sync.aligned.m8n8.x4.shared.b16 {%0,%1,%2,%3}, [%4];"
                             : "=r"(al[mi][0]), "=r"(al[mi][1]), "=r"(al[mi][2]), "=r"(al[mi][3])
                             : "r"(ad2));
            }
#pragma unroll
            for (int ni = 0; ni < 4; ni++) {
                int row = k16 + (lane & 15);
                int col = warp_n * 32 + ni * 8;
                uint32_t bd = bs_h_base + (uint32_t)(row * BS + col) * 2;
                asm volatile("ldmatrix.sync.aligned.m8n8.x2.trans.shared.b16 {%0,%1}, [%2];"
                             : "=r"(bh[ni][0]), "=r"(bh[ni][1]) : "r"(bd));
                uint32_t bd2 = bs_l_base + (uint32_t)(row * BS + col) * 2;
                asm volatile("ldmatrix.sync.aligned.m8n8.x2.trans.shared.b16 {%0,%1}, [%2];"
                             : "=r"(bl[ni][0]), "=r"(bl[ni][1]) : "r"(bd2));
            }
#pragma unroll
            for (int mi = 0; mi < 4; mi++) {
#pragma unroll
                for (int ni = 0; ni < 4; ni++) {
                    float* d = acc[mi][ni];
                    asm volatile(
                        "mma.sync.aligned.m16n8k16.row.col.f32.bf16.bf16.f32 "
                        "{%0,%1,%2,%3}, {%4,%5,%6,%7}, {%8,%9}, {%0,%1,%2,%3};"
                        : "+f"(d[0]), "+f"(d[1]), "+f"(d[2]), "+f"(d[3])
                        : "r"(ah[mi][0]), "r"(ah[mi][1]), "r"(ah[mi][2]), "r"(ah[mi][3]),
                          "r"(bh[ni][0]), "r"(bh[ni][1]));
                    asm volatile(
                        "mma.sync.aligned.m16n8k16.row.col.f32.bf16.bf16.f32 "
                        "{%0,%1,%2,%3}, {%4,%5,%6,%7}, {%8,%9}, {%0,%1,%2,%3};"
                        : "+f"(d[0]), "+f"(d[1]), "+f"(d[2]), "+f"(d[3])
                        : "r"(ah[mi][0]), "r"(ah[mi][1]), "r"(ah[mi][2]), "r"(ah[mi][3]),
                          "r"(bl[ni][0]), "r"(bl[ni][1]));
                    asm volatile(
                        "mma.sync.aligned.m16n8k16.row.col.f32.bf16.bf16.f32 "
                        "{%0,%1,%2,%3}, {%4,%5,%6,%7}, {%8,%9}, {%0,%1,%2,%3};"
                        : "+f"(d[0]), "+f"(d[1]), "+f"(d[2]), "+f"(d[3])
                        : "r"(al[mi][0]), "r"(al[mi][1]), "r"(al[mi][2]), "r"(al[mi][3]),
                          "r"(bh[ni][0]), "r"(bh[ni][1]));
                }
            }
        }
        __syncthreads();
    }

#pragma unroll
    for (int mi = 0; mi < 4; mi++) {
#pragma unroll
        for (int ni = 0; ni < 4; ni++) {
            int r0 = bm + warp_m * 64 + mi * 16 + (lane >> 2);
            int c0 = bn + warp_n * 32 + ni * 8 + (lane & 3) * 2;
            float b0 = bias[c0], b1 = bias[c0 + 1];
            float* d = acc[mi][ni];
            float2 v0 = make_float2(d[0] + b0, d[1] + b1);
            float2 v1 = make_float2(d[2] + b0, d[3] + b1);
            if (relu) {
                v0.x = fmaxf(v0.x, 0.f); v0.y = fmaxf(v0.y, 0.f);
                v1.x = fmaxf(v1.x, 0.f); v1.y = fmaxf(v1.y, 0.f);
            }
            if (r0 < M) *(float2*)&C[(size_t)r0 * D + c0] = v0;
            if (r0 + 8 < M) *(float2*)&C[(size_t)(r0 + 8) * D + c0] = v1;
        }
    }
}

// ---------------- driver ----------------
extern "C" void kernel_launch(void* const* d_in, const int* in_sizes, int n_in,
                              void* d_out, int out_size) {
    const float* x = (const float*)d_in[0];
    const int* ei = (const int*)d_in[1];   // int32 (JAX x64 disabled)
    const float* g0 = (const float*)d_in[2];
    const float* b0 = (const float*)d_in[3];
    const float* W1a = (const float*)d_in[4];
    const float* b1a = (const float*)d_in[5];
    const float* g1 = (const float*)d_in[6];
    const float* bt1 = (const float*)d_in[7];
    const float* W1b = (const float*)d_in[8];
    const float* b1b = (const float*)d_in[9];
    const float* W2a = (const float*)d_in[10];
    const float* b2a = (const float*)d_in[11];
    const float* g2 = (const float*)d_in[12];
    const float* bt2 = (const float*)d_in[13];
    const float* W2b = (const float*)d_in[14];
    const float* b2b = (const float*)d_in[15];
    float* out = (float*)d_out;

    int M = in_sizes[0] / D;
    int E = in_sizes[1] / 2;
    const int* srcI = ei;
    const int* dstI = ei + E;

    float *h, *t, *u;
    cudaGetSymbolAddress((void**)&h, g_h);
    cudaGetSymbolAddress((void**)&t, g_t);
    cudaGetSymbolAddress((void**)&u, g_u);

    long long n4 = (long long)M * (D / 4);
    const int bnGrid = 2048;
    dim3 gemmGrid((M + 127) / 128, 2);
    int aggGrid = (M + 3) / 4;
    int nb = (M + SCANB - 1) / SCANB;

    // ---- build CSR once (reused by both convs) ----
    zero_deg_kernel<<<(M + 255) / 256, 256>>>(M);
    hist_kernel<<<(E + 255) / 256, 256>>>(dstI, E);
    scan_block_kernel<<<nb, SCANB>>>(M);
    scan_bsum_kernel<<<1, 32>>>(nb);
    scan_add_kernel<<<nb, SCANB>>>(M, E);
    fill_kernel<<<(E + 255) / 256, 256>>>(srcI, dstI, E);

    // h = BN(x)
    zero_stats_kernel<<<1, 256>>>();
    stats_kernel<<<512, 256>>>(x, M);
    finalize_stats_kernel<<<1, 256>>>(g0, b0, M);
    bn_apply_kernel<<<bnGrid, 256>>>((const float4*)x, (float4*)h, n4, 0);

    // ---- conv1 ----
    agg_csr_kernel<<<aggGrid, 256>>>(h, t, M);                     // t = h + agg(h)
    gemm_tc_kernel<<<gemmGrid, 256>>>(t, W1a, b1a, u, M, 0);       // u = t@W1a + b1a
    zero_stats_kernel<<<1, 256>>>();
    stats_kernel<<<512, 256>>>(u, M);
    finalize_stats_kernel<<<1, 256>>>(g1, bt1, M);
    bn_apply_kernel<<<bnGrid, 256>>>((const float4*)u, (float4*)u, n4, 1);
    gemm_tc_kernel<<<gemmGrid, 256>>>(u, W1b, b1b, h, M, 1);       // h = relu(u@W1b+b)

    // ---- conv2 ----
    agg_csr_kernel<<<aggGrid, 256>>>(h, t, M);                     // t = h + agg(h)
    gemm_tc_kernel<<<gemmGrid, 256>>>(t, W2a, b2a, u, M, 0);
    zero_stats_kernel<<<1, 256>>>();
    stats_kernel<<<512, 256>>>(u, M);
    finalize_stats_kernel<<<1, 256>>>(g2, bt2, M);
    bn_apply_kernel<<<bnGrid, 256>>>((const float4*)u, (float4*)u, n4, 1);
    gemm_tc_kernel<<<gemmGrid, 256>>>(u, W2b, b2b, out, M, 1);     // out = relu(...)
}